// round 12
// baseline (speedup 1.0000x reference)
#include <cuda_runtime.h>
#include <cuda_fp16.h>
#include <math.h>
#include <stdint.h>

// ---------------------------------------------------------------------------
// VDP attention, round 10: projection GEMMs widened to 128x256 block /
// 64x64 warp tiles to break the smem-crossbar 1:1 wall. Fused attention
// middle unchanged (R9). B=4, N=1024, D=1024, H=16, Dh=64.
// ---------------------------------------------------------------------------

#define B_ 4
#define N_ 1024
#define D_ 1024
#define H_ 16
#define DH_ 64
#define M_ (B_ * N_)       /* 4096 rows */
#define QKV_ (3 * D_)      /* 3072 */
#define BH_ (B_ * H_)      /* 64 */
#define SCALE_ 0.125f
#define W_SCALE 4096.0f

// ------------------------- scratch (static device) -------------------------
__device__ __half g_mu_n [M_ * D_];
__device__ __half g_sg_n [M_ * D_];
__device__ __half g_m2s  [M_ * D_];
__device__ __half g_Wq_mu [QKV_ * D_];
__device__ __half g_Wq_sig[QKV_ * D_];
__device__ __half g_Wq_mu2[QKV_ * D_];
__device__ __half g_Wo_mu [D_ * D_];
__device__ __half g_Wo_sig[D_ * D_];
__device__ __half g_Wo_mu2[D_ * D_];
__device__ __half g_mu_qkv[M_ * QKV_];
__device__ __half g_sg_qkv[M_ * QKV_];
__device__ __half g_mu_o [M_ * D_];
__device__ __half g_sg_o [M_ * D_];
__device__ __half g_m2s_o[M_ * D_];

// ------------------------------ helpers ------------------------------------
__device__ __forceinline__ void mma_f16(float c[4], const uint32_t a[4],
                                        const uint32_t b[2]) {
    asm volatile(
        "mma.sync.aligned.m16n8k16.row.col.f32.f16.f16.f32 "
        "{%0,%1,%2,%3},{%4,%5,%6,%7},{%8,%9},{%0,%1,%2,%3};"
        : "+f"(c[0]), "+f"(c[1]), "+f"(c[2]), "+f"(c[3])
        : "r"(a[0]), "r"(a[1]), "r"(a[2]), "r"(a[3]), "r"(b[0]), "r"(b[1]));
}

__device__ __forceinline__ void ldsm4(uint32_t& r0, uint32_t& r1,
                                      uint32_t& r2, uint32_t& r3, uint32_t a) {
    asm volatile("ldmatrix.sync.aligned.m8n8.x4.shared.b16 {%0,%1,%2,%3}, [%4];"
                 : "=r"(r0), "=r"(r1), "=r"(r2), "=r"(r3) : "r"(a));
}
__device__ __forceinline__ void ldsm4t(uint32_t& r0, uint32_t& r1,
                                       uint32_t& r2, uint32_t& r3, uint32_t a) {
    asm volatile("ldmatrix.sync.aligned.m8n8.x4.trans.shared.b16 {%0,%1,%2,%3}, [%4];"
                 : "=r"(r0), "=r"(r1), "=r"(r2), "=r"(r3) : "r"(a));
}

__device__ __forceinline__ void cp16(void* smem_ptr, const void* g) {
    uint32_t s = (uint32_t)__cvta_generic_to_shared(smem_ptr);
    asm volatile("cp.async.cg.shared.global [%0], [%1], 16;\n" :: "r"(s), "l"(g));
}
__device__ __forceinline__ void cp_commit() {
    asm volatile("cp.async.commit_group;\n");
}
template <int N>
__device__ __forceinline__ void cp_wait() {
    asm volatile("cp.async.wait_group %0;\n" :: "n"(N));
}

__device__ __forceinline__ void store2(float* p, float x, float y) {
    *(float2*)p = make_float2(x, y);
}
__device__ __forceinline__ void store2(__half* p, float x, float y) {
    *(__half2*)p = __floats2half2_rn(x, y);
}

// ------------------------- fp16 projection GEMM core -----------------------
// C[M,N] = A1[M,K1]*B1[N,K1]^T + A2[M,K2]*B2[N,K2]^T, fp32 accum.
// BK=32 halves, 3-stage cp.async, ldmatrix frags, ONE barrier per iter.
template <typename OT, int THR, int BM, int BN, int WR, int WC>
__device__ __forceinline__ void gemm_core16(
    OT* __restrict__ C,
    const __half* __restrict__ A1, const __half* __restrict__ B1,
    const __half* __restrict__ A2, const __half* __restrict__ B2,
    int n1, int n2, int lda, int ldb, int ldc) {
    constexpr int WM = BM / WR, WN = BN / WC;
    constexpr int MT = WM / 16, NT = WN / 8;
    constexpr int PA = 40;
    constexpr int ASZ = BM * PA;
    constexpr int BSZ = BN * PA;
    constexpr int STG = ASZ + BSZ;
    constexpr int NA  = BM * 4 / THR;
    constexpr int NB  = BN * 4 / THR;

    extern __shared__ char shraw[];
    __half* sh = (__half*)shraw;
    const uint32_t sbase = (uint32_t)__cvta_generic_to_shared(sh);

    const int tid = threadIdx.x;
    const int bm = blockIdx.y * BM, bn = blockIdx.x * BN;
    const int w = tid >> 5, lane = tid & 31;
    const int gr = lane >> 2, tc = lane & 3;
    const int wm = (w / WC) * WM, wn = (w % WC) * WN;
    const int niter = n1 + n2;

    uint32_t aoff[MT], boff[NT / 2];
    #pragma unroll
    for (int ii = 0; ii < MT; ii++)
        aoff[ii] = ((wm + ii * 16 + (lane & 15)) * PA + (lane >> 4) * 8) * 2;
    #pragma unroll
    for (int j2 = 0; j2 < NT / 2; j2++)
        boff[j2] = (ASZ + (wn + j2 * 16 + (lane >> 4) * 8 + (lane & 7)) * PA
                    + ((lane >> 3) & 1) * 8) * 2;

    auto load_stage = [&](int s, int j) {
        __half* As = sh + s * STG;
        __half* Bs = As + ASZ;
        const __half* Ap; const __half* Bp; int k0;
        if (j < n1) { Ap = A1; Bp = B1; k0 = j * 32; }
        else        { Ap = A2; Bp = B2; k0 = (j - n1) * 32; }
        #pragma unroll
        for (int r = 0; r < NA; r++) {
            int idx = tid + THR * r;
            int row = idx >> 2, c = idx & 3;
            cp16(As + row * PA + c * 8,
                 Ap + (size_t)(bm + row) * lda + k0 + c * 8);
        }
        #pragma unroll
        for (int r = 0; r < NB; r++) {
            int idx = tid + THR * r;
            int row = idx >> 2, c = idx & 3;
            cp16(Bs + row * PA + c * 8,
                 Bp + (size_t)(bn + row) * ldb + k0 + c * 8);
        }
    };

    float acc[MT][NT][4] = {};

    load_stage(0, 0);
    cp_commit();
    if (niter > 1) load_stage(1, 1);
    cp_commit();

    for (int i = 0; i < niter; i++) {
        cp_wait<1>();
        __syncthreads();
        if (i + 2 < niter) load_stage((i + 2) % 3, i + 2);
        cp_commit();

        const uint32_t stg = sbase + (uint32_t)((i % 3) * STG * 2);
        #pragma unroll
        for (int g = 0; g < 2; g++) {
            uint32_t af[MT][4], bf[NT][2];
            #pragma unroll
            for (int ii = 0; ii < MT; ii++)
                ldsm4(af[ii][0], af[ii][1], af[ii][2], af[ii][3],
                      stg + aoff[ii] + g * 32);
            #pragma unroll
            for (int j2 = 0; j2 < NT / 2; j2++)
                ldsm4(bf[2 * j2][0], bf[2 * j2][1], bf[2 * j2 + 1][0],
                      bf[2 * j2 + 1][1], stg + boff[j2] + g * 32);
            #pragma unroll
            for (int ii = 0; ii < MT; ii++)
                #pragma unroll
                for (int j = 0; j < NT; j++)
                    mma_f16(acc[ii][j], af[ii], bf[j]);
        }
    }
    __syncthreads();

    #pragma unroll
    for (int ii = 0; ii < MT; ii++) {
        #pragma unroll
        for (int j = 0; j < NT; j++) {
            int row0 = bm + wm + ii * 16 + gr;
            int col  = bn + wn + j * 8 + 2 * tc;
            OT* p0 = C + (size_t)row0 * ldc + col;
            OT* p1 = C + (size_t)(row0 + 8) * ldc + col;
            store2(p0, acc[ii][j][0], acc[ii][j][1]);
            store2(p1, acc[ii][j][2], acc[ii][j][3]);
        }
    }
}

__global__ void __launch_bounds__(256, 1)
gemm16h_kernel(__half* __restrict__ C,
               const __half* __restrict__ A1, const __half* __restrict__ B1,
               const __half* __restrict__ A2, const __half* __restrict__ B2,
               int n1, int n2, int lda, int ldb, int ldc) {
    gemm_core16<__half, 256, 128, 256, 2, 4>(C, A1, B1, A2, B2,
                                             n1, n2, lda, ldb, ldc);
}

__global__ void __launch_bounds__(256, 1)
gemm16f_kernel(float* __restrict__ C,
               const __half* __restrict__ A1, const __half* __restrict__ B1,
               const __half* __restrict__ A2, const __half* __restrict__ B2,
               int n1, int n2, int lda, int ldb, int ldc) {
    gemm_core16<float, 256, 128, 256, 2, 4>(C, A1, B1, A2, B2,
                                            n1, n2, lda, ldb, ldc);
}

// ----------------------- fused attention kernel ----------------------------
// One CTA = (bh, 32-row i-block). Phases:
//  P1 dots-mu (S in 128 regs) -> softmax -> p (fp16) to smem
//  P2 PV-mu (A=p from smem via ldsm, V streamed via cp.async + ldsm.trans)
//  P3 dots-sg -> w = (p(1-p))^2*S_sg*W_SCALE, overwrites p in smem
//  P4 PV-sg -> O_sg/W_SCALE; also m2s_o = o_mu^2 + o_sg (fp16-rounded).
#define FA_P_OFF   0
#define FA_Q_OFF   66048
#define FA_STG_OFF 75264
#define FA_RED_OFF 130560
#define FA_SMEM    131584

__global__ void __launch_bounds__(256)
fused_attn_kernel() {
    extern __shared__ char sm[];
    __half* smp = (__half*)(sm + FA_P_OFF);
    __half* smq = (__half*)(sm + FA_Q_OFF);
    __half* stg = (__half*)(sm + FA_STG_OFF);
    float*  red = (float*)(sm + FA_RED_OFF);
    const uint32_t smpb = (uint32_t)__cvta_generic_to_shared(smp);
    const uint32_t smqb = (uint32_t)__cvta_generic_to_shared(smq);
    const uint32_t stgb = (uint32_t)__cvta_generic_to_shared(stg);

    const int iblk = blockIdx.x;
    const int bh   = blockIdx.y;
    const int b = bh >> 4, h = bh & 15;
    const int tid = threadIdx.x, w = tid >> 5, lane = tid & 31;
    const int gr = lane >> 2, tc = lane & 3;

    const size_t rowbase = (size_t)(b * N_ + iblk * 32);
    const __half* Qmu = g_mu_qkv + rowbase * QKV_ + h * DH_;
    const __half* Qsg = g_sg_qkv + rowbase * QKV_ + h * DH_;
    const __half* Kmu = g_mu_qkv + (size_t)b * N_ * QKV_ + D_ + h * DH_;
    const __half* Ksg = g_sg_qkv + (size_t)b * N_ * QKV_ + D_ + h * DH_;
    const __half* Vmu = g_mu_qkv + (size_t)b * N_ * QKV_ + 2 * D_ + h * DH_;
    const __half* Vsg = g_sg_qkv + (size_t)b * N_ * QKV_ + 2 * D_ + h * DH_;

    auto load_kv = [&](int s, const __half* src, int jt) {
        #pragma unroll
        for (int rr = 0; rr < 4; rr++) {
            int idx = tid + 256 * rr;
            int r = idx >> 3, c = idx & 7;
            cp16(stg + s * 9216 + r * 72 + c * 8,
                 src + (size_t)(jt * 128 + r) * QKV_ + c * 8);
        }
    };

    float acc[8][2][2][4];

    auto dots_pass = [&](const __half* Ksrc, uint32_t smqB, bool firstQ) {
        #pragma unroll
        for (int jt = 0; jt < 8; jt++)
            #pragma unroll
            for (int mi = 0; mi < 2; mi++)
                #pragma unroll
                for (int ni = 0; ni < 2; ni++)
                    #pragma unroll
                    for (int cc = 0; cc < 4; cc++) acc[jt][mi][ni][cc] = 0.0f;

        if (firstQ) {
            int row = tid >> 3, c = tid & 7;
            cp16(smq + row * 72 + c * 8, Qmu + (size_t)row * QKV_ + c * 8);
            cp16(smq + 32 * 72 + row * 72 + c * 8, Qsg + (size_t)row * QKV_ + c * 8);
        }
        load_kv(0, Ksrc, 0);
        cp_commit();
        load_kv(1, Ksrc, 1);
        cp_commit();
        cp_wait<1>();
        __syncthreads();

        uint32_t af[4][2][4];
        #pragma unroll
        for (int g = 0; g < 4; g++)
            #pragma unroll
            for (int mi = 0; mi < 2; mi++)
                ldsm4(af[g][mi][0], af[g][mi][1], af[g][mi][2], af[g][mi][3],
                      smqB + (uint32_t)(((mi * 16 + (lane & 15)) * 72
                                         + g * 16 + (lane >> 4) * 8) * 2));

        #pragma unroll
        for (int jt = 0; jt < 8; jt++) {
            if (jt) { cp_wait<1>(); __syncthreads(); }
            if (jt + 2 < 8) load_kv((jt + 2) % 3, Ksrc, jt + 2);
            cp_commit();
            const uint32_t sb = stgb + (uint32_t)((jt % 3) * 18432);
            #pragma unroll
            for (int g = 0; g < 4; g++) {
                uint32_t bf[2][2];
                ldsm4(bf[0][0], bf[0][1], bf[1][0], bf[1][1],
                      sb + (uint32_t)(((w * 16 + (lane >> 4) * 8 + (lane & 7)) * 72
                                       + ((lane >> 3) & 1) * 8 + g * 16) * 2));
                #pragma unroll
                for (int mi = 0; mi < 2; mi++)
                    #pragma unroll
                    for (int ni = 0; ni < 2; ni++)
                        mma_f16(acc[jt][mi][ni], af[g][mi], bf[ni]);
            }
        }
        cp_wait<0>();
        __syncthreads();
    };

    const int rwarp = w >> 2, cwarp = w & 3;
    float oacc[2][4];
    auto pv_pass = [&](const __half* Vsrc) {
        #pragma unroll
        for (int ni = 0; ni < 2; ni++)
            #pragma unroll
            for (int cc = 0; cc < 4; cc++) oacc[ni][cc] = 0.0f;
        load_kv(0, Vsrc, 0);
        cp_commit();
        load_kv(1, Vsrc, 1);
        cp_commit();
        #pragma unroll
        for (int jt = 0; jt < 8; jt++) {
            cp_wait<1>();
            __syncthreads();
            if (jt + 2 < 8) load_kv((jt + 2) % 3, Vsrc, jt + 2);
            cp_commit();
            const uint32_t sb = stgb + (uint32_t)((jt % 3) * 18432);
            #pragma unroll
            for (int s = 0; s < 8; s++) {
                uint32_t a4[4], bf[2][2];
                ldsm4(a4[0], a4[1], a4[2], a4[3],
                      smpb + (uint32_t)(((rwarp * 16 + (lane & 15)) * 1032
                                         + jt * 128 + s * 16 + (lane >> 4) * 8) * 2));
                ldsm4t(bf[0][0], bf[0][1], bf[1][0], bf[1][1],
                       sb + (uint32_t)(((s * 16 + (lane & 7) + ((lane >> 3) & 1) * 8) * 72
                                        + cwarp * 16 + (lane >> 4) * 8) * 2));
                mma_f16(oacc[0], a4, bf[0]);
                mma_f16(oacc[1], a4, bf[1]);
            }
        }
        cp_wait<0>();
        __syncthreads();
    };

    // ================= P1: dots-mu + softmax -> p ==========================
    dots_pass(Kmu, smqb, true);

    float mx[4] = {-1e30f, -1e30f, -1e30f, -1e30f};
    #pragma unroll
    for (int jt = 0; jt < 8; jt++)
        #pragma unroll
        for (int mi = 0; mi < 2; mi++)
            #pragma unroll
            for (int ni = 0; ni < 2; ni++)
                #pragma unroll
                for (int cc = 0; cc < 4; cc++) {
                    float s = acc[jt][mi][ni][cc] * SCALE_;
                    acc[jt][mi][ni][cc] = s;
                    mx[mi * 2 + (cc >> 1)] = fmaxf(mx[mi * 2 + (cc >> 1)], s);
                }
    #pragma unroll
    for (int rr = 0; rr < 4; rr++) {
        mx[rr] = fmaxf(mx[rr], __shfl_xor_sync(0xffffffffu, mx[rr], 1));
        mx[rr] = fmaxf(mx[rr], __shfl_xor_sync(0xffffffffu, mx[rr], 2));
    }
    if (tc == 0)
        #pragma unroll
        for (int rr = 0; rr < 4; rr++) red[(rr * 8 + gr) * 8 + w] = mx[rr];
    __syncthreads();
    #pragma unroll
    for (int rr = 0; rr < 4; rr++) {
        float m = red[(rr * 8 + gr) * 8];
        #pragma unroll
        for (int q = 1; q < 8; q++) m = fmaxf(m, red[(rr * 8 + gr) * 8 + q]);
        mx[rr] = m;
    }
    __syncthreads();

    float sum[4] = {0.f, 0.f, 0.f, 0.f};
    #pragma unroll
    for (int jt = 0; jt < 8; jt++)
        #pragma unroll
        for (int mi = 0; mi < 2; mi++)
            #pragma unroll
            for (int ni = 0; ni < 2; ni++)
                #pragma unroll
                for (int cc = 0; cc < 4; cc++) {
                    int rr = mi * 2 + (cc >> 1);
                    float e = __expf(acc[jt][mi][ni][cc] - mx[rr]);
                    acc[jt][mi][ni][cc] = e;
                    sum[rr] += e;
                }
    #pragma unroll
    for (int rr = 0; rr < 4; rr++) {
        sum[rr] += __shfl_xor_sync(0xffffffffu, sum[rr], 1);
        sum[rr] += __shfl_xor_sync(0xffffffffu, sum[rr], 2);
    }
    if (tc == 0)
        #pragma unroll
        for (int rr = 0; rr < 4; rr++) red[(rr * 8 + gr) * 8 + w] = sum[rr];
    __syncthreads();
    float inv[4];
    #pragma unroll
    for (int rr = 0; rr < 4; rr++) {
        float z = red[(rr * 8 + gr) * 8];
        #pragma unroll
        for (int q = 1; q < 8; q++) z += red[(rr * 8 + gr) * 8 + q];
        inv[rr] = 1.0f / z;
    }
    #pragma unroll
    for (int jt = 0; jt < 8; jt++)
        #pragma unroll
        for (int mi = 0; mi < 2; mi++)
            #pragma unroll
            for (int ni = 0; ni < 2; ni++) {
                int col = jt * 128 + w * 16 + ni * 8 + 2 * tc;
                int r0 = mi * 16 + gr, r1 = mi * 16 + 8 + gr;
                *(__half2*)&smp[r0 * 1032 + col] = __floats2half2_rn(
                    acc[jt][mi][ni][0] * inv[mi * 2], acc[jt][mi][ni][1] * inv[mi * 2]);
                *(__half2*)&smp[r1 * 1032 + col] = __floats2half2_rn(
                    acc[jt][mi][ni][2] * inv[mi * 2 + 1], acc[jt][mi][ni][3] * inv[mi * 2 + 1]);
            }
    __syncthreads();

    // ================= P2: O_mu = p @ V_mu =================================
    pv_pass(Vmu);
    const int grow = b * N_ + iblk * 32 + rwarp * 16 + gr;
    const int gcolb = h * DH_ + cwarp * 16;
    __half2 omu_h[2][2];
    #pragma unroll
    for (int ni = 0; ni < 2; ni++) {
        omu_h[ni][0] = __floats2half2_rn(oacc[ni][0], oacc[ni][1]);
        omu_h[ni][1] = __floats2half2_rn(oacc[ni][2], oacc[ni][3]);
        int gcol = gcolb + ni * 8 + 2 * tc;
        *(__half2*)&g_mu_o[(size_t)grow * D_ + gcol]       = omu_h[ni][0];
        *(__half2*)&g_mu_o[(size_t)(grow + 8) * D_ + gcol] = omu_h[ni][1];
    }

    // ================= P3: dots-sg -> w (overwrite p in smem) ==============
    dots_pass(Ksg, smqb + 32 * 72 * 2, false);
    #pragma unroll
    for (int jt = 0; jt < 8; jt++)
        #pragma unroll
        for (int mi = 0; mi < 2; mi++)
            #pragma unroll
            for (int ni = 0; ni < 2; ni++) {
                int col = jt * 128 + w * 16 + ni * 8 + 2 * tc;
                #pragma unroll
                for (int half = 0; half < 2; half++) {
                    int row = mi * 16 + half * 8 + gr;
                    __half2 ph = *(__half2*)&smp[row * 1032 + col];
                    float p0 = __low2float(ph), p1 = __high2float(ph);
                    float j0 = p0 * (1.0f - p0), j1 = p1 * (1.0f - p1);
                    float w0 = j0 * j0 * acc[jt][mi][ni][2 * half] * SCALE_ * W_SCALE;
                    float w1 = j1 * j1 * acc[jt][mi][ni][2 * half + 1] * SCALE_ * W_SCALE;
                    *(__half2*)&smp[row * 1032 + col] = __floats2half2_rn(w0, w1);
                }
            }
    __syncthreads();

    // ================= P4: O_sg = w @ V_sg / W_SCALE + m2s_o ===============
    pv_pass(Vsg);
    #pragma unroll
    for (int ni = 0; ni < 2; ni++) {
        __half2 s01 = __floats2half2_rn(oacc[ni][0] * (1.0f / W_SCALE),
                                        oacc[ni][1] * (1.0f / W_SCALE));
        __half2 s23 = __floats2half2_rn(oacc[ni][2] * (1.0f / W_SCALE),
                                        oacc[ni][3] * (1.0f / W_SCALE));
        int gcol = gcolb + ni * 8 + 2 * tc;
        *(__half2*)&g_sg_o[(size_t)grow * D_ + gcol]       = s01;
        *(__half2*)&g_sg_o[(size_t)(grow + 8) * D_ + gcol] = s23;
        float2 mf0 = __half22float2(omu_h[ni][0]);
        float2 mf1 = __half22float2(omu_h[ni][1]);
        float2 sf0 = __half22float2(s01);
        float2 sf1 = __half22float2(s23);
        *(__half2*)&g_m2s_o[(size_t)grow * D_ + gcol] =
            __floats2half2_rn(fmaf(mf0.x, mf0.x, sf0.x), fmaf(mf0.y, mf0.y, sf0.y));
        *(__half2*)&g_m2s_o[(size_t)(grow + 8) * D_ + gcol] =
            __floats2half2_rn(fmaf(mf1.x, mf1.x, sf1.x), fmaf(mf1.y, mf1.y, sf1.y));
    }
}

// ------------------------------ prep weights -------------------------------
__device__ __forceinline__ float softplusf(float x) {
    return fmaxf(x, 0.0f) + log1pf(expf(-fabsf(x)));
}

__global__ void prep_weights_kernel(const float* __restrict__ Wqkv_mu,
                                    const float* __restrict__ Wqkv_raw,
                                    const float* __restrict__ Wout_mu,
                                    const float* __restrict__ Wout_raw) {
    int i = blockIdx.x * blockDim.x + threadIdx.x;
    const int nq2 = QKV_ * D_ / 2;
    if (i < nq2) {
        int e = 2 * i;
        float w0 = Wqkv_mu[e], w1 = Wqkv_mu[e + 1];
        *(__half2*)(g_Wq_mu  + e) = __floats2half2_rn(w0, w1);
        *(__half2*)(g_Wq_mu2 + e) = __floats2half2_rn(w0 * w0, w1 * w1);
        *(__half2*)(g_Wq_sig + e) = __floats2half2_rn(softplusf(Wqkv_raw[e]),
                                                      softplusf(Wqkv_raw[e + 1]));
    } else {
        int e = 2 * (i - nq2);
        if (e < D_ * D_) {
            float w0 = Wout_mu[e], w1 = Wout_mu[e + 1];
            *(__half2*)(g_Wo_mu  + e) = __floats2half2_rn(w0, w1);
            *(__half2*)(g_Wo_mu2 + e) = __floats2half2_rn(w0 * w0, w1 * w1);
            *(__half2*)(g_Wo_sig + e) = __floats2half2_rn(softplusf(Wout_raw[e]),
                                                          softplusf(Wout_raw[e + 1]));
        }
    }
}

// -------------------------------- layernorm --------------------------------
__global__ void layernorm_kernel(const float* __restrict__ mu,
                                 const float* __restrict__ sigma,
                                 const float* __restrict__ gamma,
                                 const float* __restrict__ beta) {
    const int row = blockIdx.x;
    const int t   = threadIdx.x;
    float4 m = ((const float4*)(mu + (size_t)row * D_))[t];

    float s  = m.x + m.y + m.z + m.w;
    float sq = m.x * m.x + m.y * m.y + m.z * m.z + m.w * m.w;

    __shared__ float red[256];
    red[t] = s; __syncthreads();
    #pragma unroll
    for (int o = 128; o > 0; o >>= 1) { if (t < o) red[t] += red[t + o]; __syncthreads(); }
    float mean = red[0] * (1.0f / D_);
    __syncthreads();
    red[t] = sq; __syncthreads();
    #pragma unroll
    for (int o = 128; o > 0; o >>= 1) { if (t < o) red[t] += red[t + o]; __syncthreads(); }
    float var = red[0] * (1.0f / D_) - mean * mean;
    float inv = rsqrtf(var + 1e-5f);

    const float4 sg = ((const float4*)(sigma + (size_t)row * D_))[t];
    const float4 gm = ((const float4*)gamma)[t];
    const float4 bt = ((const float4*)beta)[t];

    float4 mo, so, m2;
    mo.x = (m.x - mean) * inv * gm.x + bt.x;  so.x = sg.x * gm.x * gm.x * inv * inv;  m2.x = fmaf(mo.x, mo.x, so.x);
    mo.y = (m.y - mean) * inv * gm.y + bt.y;  so.y = sg.y * gm.y * gm.y * inv * inv;  m2.y = fmaf(mo.y, mo.y, so.y);
    mo.z = (m.z - mean) * inv * gm.z + bt.z;  so.z = sg.z * gm.z * gm.z * inv * inv;  m2.z = fmaf(mo.z, mo.z, so.z);
    mo.w = (m.w - mean) * inv * gm.w + bt.w;  so.w = sg.w * gm.w * gm.w * inv * inv;  m2.w = fmaf(mo.w, mo.w, so.w);

    const int e = row * D_ + t * 4;
    *(__half2*)(g_mu_n + e)     = __floats2half2_rn(mo.x, mo.y);
    *(__half2*)(g_mu_n + e + 2) = __floats2half2_rn(mo.z, mo.w);
    *(__half2*)(g_sg_n + e)     = __floats2half2_rn(so.x, so.y);
    *(__half2*)(g_sg_n + e + 2) = __floats2half2_rn(so.z, so.w);
    *(__half2*)(g_m2s + e)      = __floats2half2_rn(m2.x, m2.y);
    *(__half2*)(g_m2s + e + 2)  = __floats2half2_rn(m2.z, m2.w);
}

// --------------------------------- launch ----------------------------------
extern "C" void kernel_launch(void* const* d_in, const int* in_sizes, int n_in,
                              void* d_out, int out_size) {
    (void)in_sizes; (void)n_in; (void)out_size;
    const float* mu       = (const float*)d_in[0];
    const float* sigma    = (const float*)d_in[1];
    const float* gamma    = (const float*)d_in[2];
    const float* beta     = (const float*)d_in[3];
    const float* Wqkv_mu  = (const float*)d_in[4];
    const float* Wqkv_raw = (const float*)d_in[5];
    const float* Wout_mu  = (const float*)d_in[6];
    const float* Wout_raw = (const float*)d_in[7];
    float* out = (float*)d_out;

    __half *p_mu_n, *p_sg_n, *p_m2s, *p_wq_mu, *p_wq_sig, *p_wq_mu2;
    __half *p_wo_mu, *p_wo_sig, *p_wo_mu2, *p_mu_qkv, *p_sg_qkv;
    __half *p_mu_o, *p_sg_o, *p_m2so;
    cudaGetSymbolAddress((void**)&p_mu_n,   g_mu_n);
    cudaGetSymbolAddress((void**)&p_sg_n,   g_sg_n);
    cudaGetSymbolAddress((void**)&p_m2s,    g_m2s);
    cudaGetSymbolAddress((void**)&p_wq_mu,  g_Wq_mu);
    cudaGetSymbolAddress((void**)&p_wq_sig, g_Wq_sig);
    cudaGetSymbolAddress((void**)&p_wq_mu2, g_Wq_mu2);
    cudaGetSymbolAddress((void**)&p_wo_mu,  g_Wo_mu);
    cudaGetSymbolAddress((void**)&p_wo_sig, g_Wo_sig);
    cudaGetSymbolAddress((void**)&p_wo_mu2, g_Wo_mu2);
    cudaGetSymbolAddress((void**)&p_mu_qkv, g_mu_qkv);
    cudaGetSymbolAddress((void**)&p_sg_qkv, g_sg_qkv);
    cudaGetSymbolAddress((void**)&p_mu_o,   g_mu_o);
    cudaGetSymbolAddress((void**)&p_sg_o,   g_sg_o);
    cudaGetSymbolAddress((void**)&p_m2so,   g_m2s_o);

    const int S_BIG = 3 * (128 * 40 + 256 * 40) * 2;   // 92160 B
    cudaFuncSetAttribute(gemm16h_kernel, cudaFuncAttributeMaxDynamicSharedMemorySize, S_BIG);
    cudaFuncSetAttribute(gemm16f_kernel, cudaFuncAttributeMaxDynamicSharedMemorySize, S_BIG);
    cudaFuncSetAttribute(fused_attn_kernel, cudaFuncAttributeMaxDynamicSharedMemorySize, FA_SMEM);

    // 1. weight transforms -> fp16
    prep_weights_kernel<<<(QKV_ * D_ + D_ * D_) / 2 / 256, 256>>>(
        Wqkv_mu, Wqkv_raw, Wout_mu, Wout_raw);

    // 2. layernorm (+ mu^2+sigma) -> fp16
    layernorm_kernel<<<M_, 256>>>(mu, sigma, gamma, beta);

    // 3. QKV projections: mu, then fused sigma
    dim3 gq(QKV_ / 256, M_ / 128);
    gemm16h_kernel<<<gq, 256, S_BIG>>>(p_mu_qkv, p_mu_n, p_wq_mu,
                                       p_mu_n, p_wq_mu, 32, 0, D_, D_, QKV_);
    gemm16h_kernel<<<gq, 256, S_BIG>>>(p_sg_qkv, p_m2s, p_wq_sig,
                                       p_sg_n, p_wq_mu2, 32, 32, D_, D_, QKV_);

    // 4-7. fused attention middle (dots, softmax, PV, m2s_o)
    fused_attn_kernel<<<dim3(N_ / 32, BH_), 256, FA_SMEM>>>();

    // 8. output projection -> fp32 d_out (sigma fused)
    dim3 go(D_ / 256, M_ / 128);
    gemm16f_kernel<<<go, 256, S_BIG>>>(out, p_mu_o, p_wo_mu,
                                       p_mu_o, p_wo_mu, 32, 0, D_, D_, D_);
    gemm16f_kernel<<<go, 256, S_BIG>>>(out + M_ * D_, p_m2so, p_wo_sig,
                                       p_sg_o, p_wo_mu2, 32, 32, D_, D_, D_);
}

// round 15
// speedup vs baseline: 1.1121x; 1.1121x over previous
#include <cuda_runtime.h>
#include <cuda_fp16.h>
#include <math.h>
#include <stdint.h>

// ---------------------------------------------------------------------------
// VDP attention, round 12: R9 GEMM config (128x128, best measured) with
// mu/sigma projection pairs MERGED into single launches (blockIdx.z picks
// the job) to kill wave-quantization tails. Fused attention middle = R9.
// B=4, N=1024, D=1024, H=16, Dh=64.
// ---------------------------------------------------------------------------

#define B_ 4
#define N_ 1024
#define D_ 1024
#define H_ 16
#define DH_ 64
#define M_ (B_ * N_)       /* 4096 rows */
#define QKV_ (3 * D_)      /* 3072 */
#define BH_ (B_ * H_)      /* 64 */
#define SCALE_ 0.125f
#define W_SCALE 4096.0f

// ------------------------- scratch (static device) -------------------------
__device__ __half g_mu_n [M_ * D_];
__device__ __half g_sg_n [M_ * D_];
__device__ __half g_m2s  [M_ * D_];
__device__ __half g_Wq_mu [QKV_ * D_];
__device__ __half g_Wq_sig[QKV_ * D_];
__device__ __half g_Wq_mu2[QKV_ * D_];
__device__ __half g_Wo_mu [D_ * D_];
__device__ __half g_Wo_sig[D_ * D_];
__device__ __half g_Wo_mu2[D_ * D_];
__device__ __half g_mu_qkv[M_ * QKV_];
__device__ __half g_sg_qkv[M_ * QKV_];
__device__ __half g_mu_o [M_ * D_];
__device__ __half g_sg_o [M_ * D_];
__device__ __half g_m2s_o[M_ * D_];

// ------------------------------ helpers ------------------------------------
__device__ __forceinline__ void mma_f16(float c[4], const uint32_t a[4],
                                        const uint32_t b[2]) {
    asm volatile(
        "mma.sync.aligned.m16n8k16.row.col.f32.f16.f16.f32 "
        "{%0,%1,%2,%3},{%4,%5,%6,%7},{%8,%9},{%0,%1,%2,%3};"
        : "+f"(c[0]), "+f"(c[1]), "+f"(c[2]), "+f"(c[3])
        : "r"(a[0]), "r"(a[1]), "r"(a[2]), "r"(a[3]), "r"(b[0]), "r"(b[1]));
}

__device__ __forceinline__ void ldsm4(uint32_t& r0, uint32_t& r1,
                                      uint32_t& r2, uint32_t& r3, uint32_t a) {
    asm volatile("ldmatrix.sync.aligned.m8n8.x4.shared.b16 {%0,%1,%2,%3}, [%4];"
                 : "=r"(r0), "=r"(r1), "=r"(r2), "=r"(r3) : "r"(a));
}
__device__ __forceinline__ void ldsm4t(uint32_t& r0, uint32_t& r1,
                                       uint32_t& r2, uint32_t& r3, uint32_t a) {
    asm volatile("ldmatrix.sync.aligned.m8n8.x4.trans.shared.b16 {%0,%1,%2,%3}, [%4];"
                 : "=r"(r0), "=r"(r1), "=r"(r2), "=r"(r3) : "r"(a));
}

__device__ __forceinline__ void cp16(void* smem_ptr, const void* g) {
    uint32_t s = (uint32_t)__cvta_generic_to_shared(smem_ptr);
    asm volatile("cp.async.cg.shared.global [%0], [%1], 16;\n" :: "r"(s), "l"(g));
}
__device__ __forceinline__ void cp_commit() {
    asm volatile("cp.async.commit_group;\n");
}
template <int N>
__device__ __forceinline__ void cp_wait() {
    asm volatile("cp.async.wait_group %0;\n" :: "n"(N));
}

__device__ __forceinline__ void store2(float* p, float x, float y) {
    *(float2*)p = make_float2(x, y);
}
__device__ __forceinline__ void store2(__half* p, float x, float y) {
    *(__half2*)p = __floats2half2_rn(x, y);
}

// ------------------------- fp16 projection GEMM core -----------------------
// C[M,N] = A1[M,K1]*B1[N,K1]^T + A2[M,K2]*B2[N,K2]^T, fp32 accum.
// BK=32 halves, 3-stage cp.async, ldmatrix frags, ONE barrier per iter.
template <typename OT, int THR, int BM, int BN, int WR, int WC>
__device__ __forceinline__ void gemm_core16(
    OT* __restrict__ C,
    const __half* __restrict__ A1, const __half* __restrict__ B1,
    const __half* __restrict__ A2, const __half* __restrict__ B2,
    int n1, int n2, int lda, int ldb, int ldc) {
    constexpr int WM = BM / WR, WN = BN / WC;
    constexpr int MT = WM / 16, NT = WN / 8;
    constexpr int PA = 40;
    constexpr int ASZ = BM * PA;
    constexpr int BSZ = BN * PA;
    constexpr int STG = ASZ + BSZ;
    constexpr int NA  = BM * 4 / THR;
    constexpr int NB  = BN * 4 / THR;

    extern __shared__ char shraw[];
    __half* sh = (__half*)shraw;
    const uint32_t sbase = (uint32_t)__cvta_generic_to_shared(sh);

    const int tid = threadIdx.x;
    const int bm = blockIdx.y * BM, bn = blockIdx.x * BN;
    const int w = tid >> 5, lane = tid & 31;
    const int gr = lane >> 2, tc = lane & 3;
    const int wm = (w / WC) * WM, wn = (w % WC) * WN;
    const int niter = n1 + n2;

    uint32_t aoff[MT], boff[NT / 2];
    #pragma unroll
    for (int ii = 0; ii < MT; ii++)
        aoff[ii] = ((wm + ii * 16 + (lane & 15)) * PA + (lane >> 4) * 8) * 2;
    #pragma unroll
    for (int j2 = 0; j2 < NT / 2; j2++)
        boff[j2] = (ASZ + (wn + j2 * 16 + (lane >> 4) * 8 + (lane & 7)) * PA
                    + ((lane >> 3) & 1) * 8) * 2;

    auto load_stage = [&](int s, int j) {
        __half* As = sh + s * STG;
        __half* Bs = As + ASZ;
        const __half* Ap; const __half* Bp; int k0;
        if (j < n1) { Ap = A1; Bp = B1; k0 = j * 32; }
        else        { Ap = A2; Bp = B2; k0 = (j - n1) * 32; }
        #pragma unroll
        for (int r = 0; r < NA; r++) {
            int idx = tid + THR * r;
            int row = idx >> 2, c = idx & 3;
            cp16(As + row * PA + c * 8,
                 Ap + (size_t)(bm + row) * lda + k0 + c * 8);
        }
        #pragma unroll
        for (int r = 0; r < NB; r++) {
            int idx = tid + THR * r;
            int row = idx >> 2, c = idx & 3;
            cp16(Bs + row * PA + c * 8,
                 Bp + (size_t)(bn + row) * ldb + k0 + c * 8);
        }
    };

    float acc[MT][NT][4] = {};

    load_stage(0, 0);
    cp_commit();
    if (niter > 1) load_stage(1, 1);
    cp_commit();

    for (int i = 0; i < niter; i++) {
        cp_wait<1>();
        __syncthreads();
        if (i + 2 < niter) load_stage((i + 2) % 3, i + 2);
        cp_commit();

        const uint32_t stg = sbase + (uint32_t)((i % 3) * STG * 2);
        #pragma unroll
        for (int g = 0; g < 2; g++) {
            uint32_t af[MT][4], bf[NT][2];
            #pragma unroll
            for (int ii = 0; ii < MT; ii++)
                ldsm4(af[ii][0], af[ii][1], af[ii][2], af[ii][3],
                      stg + aoff[ii] + g * 32);
            #pragma unroll
            for (int j2 = 0; j2 < NT / 2; j2++)
                ldsm4(bf[2 * j2][0], bf[2 * j2][1], bf[2 * j2 + 1][0],
                      bf[2 * j2 + 1][1], stg + boff[j2] + g * 32);
            #pragma unroll
            for (int ii = 0; ii < MT; ii++)
                #pragma unroll
                for (int j = 0; j < NT; j++)
                    mma_f16(acc[ii][j], af[ii], bf[j]);
        }
    }
    __syncthreads();

    #pragma unroll
    for (int ii = 0; ii < MT; ii++) {
        #pragma unroll
        for (int j = 0; j < NT; j++) {
            int row0 = bm + wm + ii * 16 + gr;
            int col  = bn + wn + j * 8 + 2 * tc;
            OT* p0 = C + (size_t)row0 * ldc + col;
            OT* p1 = C + (size_t)(row0 + 8) * ldc + col;
            store2(p0, acc[ii][j][0], acc[ii][j][1]);
            store2(p1, acc[ii][j][2], acc[ii][j][3]);
        }
    }
}

// Dual-job wrappers: blockIdx.z selects job. z=0 should carry the LONGER job.
struct GemmJobH {
    __half* C;
    const __half *A1, *B1, *A2, *B2;
    int n1, n2;
};
struct GemmJobF {
    float* C;
    const __half *A1, *B1, *A2, *B2;
    int n1, n2;
};

__global__ void __launch_bounds__(256)
gemm16h_dual_kernel(GemmJobH j0, GemmJobH j1, int lda, int ldb, int ldc) {
    GemmJobH j = blockIdx.z ? j1 : j0;
    gemm_core16<__half, 256, 128, 128, 2, 4>(j.C, j.A1, j.B1, j.A2, j.B2,
                                             j.n1, j.n2, lda, ldb, ldc);
}

__global__ void __launch_bounds__(256)
gemm16f_dual_kernel(GemmJobF j0, GemmJobF j1, int lda, int ldb, int ldc) {
    GemmJobF j = blockIdx.z ? j1 : j0;
    gemm_core16<float, 256, 128, 128, 2, 4>(j.C, j.A1, j.B1, j.A2, j.B2,
                                            j.n1, j.n2, lda, ldb, ldc);
}

// ----------------------- fused attention kernel ----------------------------
// One CTA = (bh, 32-row i-block). Phases:
//  P1 dots-mu (S in 128 regs) -> softmax -> p (fp16) to smem
//  P2 PV-mu (A=p from smem via ldsm, V streamed via cp.async + ldsm.trans)
//  P3 dots-sg -> w = (p(1-p))^2*S_sg*W_SCALE, overwrites p in smem
//  P4 PV-sg -> O_sg/W_SCALE; also m2s_o = o_mu^2 + o_sg (fp16-rounded).
#define FA_P_OFF   0
#define FA_Q_OFF   66048
#define FA_STG_OFF 75264
#define FA_RED_OFF 130560
#define FA_SMEM    131584

__global__ void __launch_bounds__(256)
fused_attn_kernel() {
    extern __shared__ char sm[];
    __half* smp = (__half*)(sm + FA_P_OFF);
    __half* smq = (__half*)(sm + FA_Q_OFF);
    __half* stg = (__half*)(sm + FA_STG_OFF);
    float*  red = (float*)(sm + FA_RED_OFF);
    const uint32_t smpb = (uint32_t)__cvta_generic_to_shared(smp);
    const uint32_t smqb = (uint32_t)__cvta_generic_to_shared(smq);
    const uint32_t stgb = (uint32_t)__cvta_generic_to_shared(stg);

    const int iblk = blockIdx.x;
    const int bh   = blockIdx.y;
    const int b = bh >> 4, h = bh & 15;
    const int tid = threadIdx.x, w = tid >> 5, lane = tid & 31;
    const int gr = lane >> 2, tc = lane & 3;

    const size_t rowbase = (size_t)(b * N_ + iblk * 32);
    const __half* Qmu = g_mu_qkv + rowbase * QKV_ + h * DH_;
    const __half* Qsg = g_sg_qkv + rowbase * QKV_ + h * DH_;
    const __half* Kmu = g_mu_qkv + (size_t)b * N_ * QKV_ + D_ + h * DH_;
    const __half* Ksg = g_sg_qkv + (size_t)b * N_ * QKV_ + D_ + h * DH_;
    const __half* Vmu = g_mu_qkv + (size_t)b * N_ * QKV_ + 2 * D_ + h * DH_;
    const __half* Vsg = g_sg_qkv + (size_t)b * N_ * QKV_ + 2 * D_ + h * DH_;

    auto load_kv = [&](int s, const __half* src, int jt) {
        #pragma unroll
        for (int rr = 0; rr < 4; rr++) {
            int idx = tid + 256 * rr;
            int r = idx >> 3, c = idx & 7;
            cp16(stg + s * 9216 + r * 72 + c * 8,
                 src + (size_t)(jt * 128 + r) * QKV_ + c * 8);
        }
    };

    float acc[8][2][2][4];

    auto dots_pass = [&](const __half* Ksrc, uint32_t smqB, bool firstQ) {
        #pragma unroll
        for (int jt = 0; jt < 8; jt++)
            #pragma unroll
            for (int mi = 0; mi < 2; mi++)
                #pragma unroll
                for (int ni = 0; ni < 2; ni++)
                    #pragma unroll
                    for (int cc = 0; cc < 4; cc++) acc[jt][mi][ni][cc] = 0.0f;

        if (firstQ) {
            int row = tid >> 3, c = tid & 7;
            cp16(smq + row * 72 + c * 8, Qmu + (size_t)row * QKV_ + c * 8);
            cp16(smq + 32 * 72 + row * 72 + c * 8, Qsg + (size_t)row * QKV_ + c * 8);
        }
        load_kv(0, Ksrc, 0);
        cp_commit();
        load_kv(1, Ksrc, 1);
        cp_commit();
        cp_wait<1>();
        __syncthreads();

        uint32_t af[4][2][4];
        #pragma unroll
        for (int g = 0; g < 4; g++)
            #pragma unroll
            for (int mi = 0; mi < 2; mi++)
                ldsm4(af[g][mi][0], af[g][mi][1], af[g][mi][2], af[g][mi][3],
                      smqB + (uint32_t)(((mi * 16 + (lane & 15)) * 72
                                         + g * 16 + (lane >> 4) * 8) * 2));

        #pragma unroll
        for (int jt = 0; jt < 8; jt++) {
            if (jt) { cp_wait<1>(); __syncthreads(); }
            if (jt + 2 < 8) load_kv((jt + 2) % 3, Ksrc, jt + 2);
            cp_commit();
            const uint32_t sb = stgb + (uint32_t)((jt % 3) * 18432);
            #pragma unroll
            for (int g = 0; g < 4; g++) {
                uint32_t bf[2][2];
                ldsm4(bf[0][0], bf[0][1], bf[1][0], bf[1][1],
                      sb + (uint32_t)(((w * 16 + (lane >> 4) * 8 + (lane & 7)) * 72
                                       + ((lane >> 3) & 1) * 8 + g * 16) * 2));
                #pragma unroll
                for (int mi = 0; mi < 2; mi++)
                    #pragma unroll
                    for (int ni = 0; ni < 2; ni++)
                        mma_f16(acc[jt][mi][ni], af[g][mi], bf[ni]);
            }
        }
        cp_wait<0>();
        __syncthreads();
    };

    const int rwarp = w >> 2, cwarp = w & 3;
    float oacc[2][4];
    auto pv_pass = [&](const __half* Vsrc) {
        #pragma unroll
        for (int ni = 0; ni < 2; ni++)
            #pragma unroll
            for (int cc = 0; cc < 4; cc++) oacc[ni][cc] = 0.0f;
        load_kv(0, Vsrc, 0);
        cp_commit();
        load_kv(1, Vsrc, 1);
        cp_commit();
        #pragma unroll
        for (int jt = 0; jt < 8; jt++) {
            cp_wait<1>();
            __syncthreads();
            if (jt + 2 < 8) load_kv((jt + 2) % 3, Vsrc, jt + 2);
            cp_commit();
            const uint32_t sb = stgb + (uint32_t)((jt % 3) * 18432);
            #pragma unroll
            for (int s = 0; s < 8; s++) {
                uint32_t a4[4], bf[2][2];
                ldsm4(a4[0], a4[1], a4[2], a4[3],
                      smpb + (uint32_t)(((rwarp * 16 + (lane & 15)) * 1032
                                         + jt * 128 + s * 16 + (lane >> 4) * 8) * 2));
                ldsm4t(bf[0][0], bf[0][1], bf[1][0], bf[1][1],
                       sb + (uint32_t)(((s * 16 + (lane & 7) + ((lane >> 3) & 1) * 8) * 72
                                        + cwarp * 16 + (lane >> 4) * 8) * 2));
                mma_f16(oacc[0], a4, bf[0]);
                mma_f16(oacc[1], a4, bf[1]);
            }
        }
        cp_wait<0>();
        __syncthreads();
    };

    // ================= P1: dots-mu + softmax -> p ==========================
    dots_pass(Kmu, smqb, true);

    float mx[4] = {-1e30f, -1e30f, -1e30f, -1e30f};
    #pragma unroll
    for (int jt = 0; jt < 8; jt++)
        #pragma unroll
        for (int mi = 0; mi < 2; mi++)
            #pragma unroll
            for (int ni = 0; ni < 2; ni++)
                #pragma unroll
                for (int cc = 0; cc < 4; cc++) {
                    float s = acc[jt][mi][ni][cc] * SCALE_;
                    acc[jt][mi][ni][cc] = s;
                    mx[mi * 2 + (cc >> 1)] = fmaxf(mx[mi * 2 + (cc >> 1)], s);
                }
    #pragma unroll
    for (int rr = 0; rr < 4; rr++) {
        mx[rr] = fmaxf(mx[rr], __shfl_xor_sync(0xffffffffu, mx[rr], 1));
        mx[rr] = fmaxf(mx[rr], __shfl_xor_sync(0xffffffffu, mx[rr], 2));
    }
    if (tc == 0)
        #pragma unroll
        for (int rr = 0; rr < 4; rr++) red[(rr * 8 + gr) * 8 + w] = mx[rr];
    __syncthreads();
    #pragma unroll
    for (int rr = 0; rr < 4; rr++) {
        float m = red[(rr * 8 + gr) * 8];
        #pragma unroll
        for (int q = 1; q < 8; q++) m = fmaxf(m, red[(rr * 8 + gr) * 8 + q]);
        mx[rr] = m;
    }
    __syncthreads();

    float sum[4] = {0.f, 0.f, 0.f, 0.f};
    #pragma unroll
    for (int jt = 0; jt < 8; jt++)
        #pragma unroll
        for (int mi = 0; mi < 2; mi++)
            #pragma unroll
            for (int ni = 0; ni < 2; ni++)
                #pragma unroll
                for (int cc = 0; cc < 4; cc++) {
                    int rr = mi * 2 + (cc >> 1);
                    float e = __expf(acc[jt][mi][ni][cc] - mx[rr]);
                    acc[jt][mi][ni][cc] = e;
                    sum[rr] += e;
                }
    #pragma unroll
    for (int rr = 0; rr < 4; rr++) {
        sum[rr] += __shfl_xor_sync(0xffffffffu, sum[rr], 1);
        sum[rr] += __shfl_xor_sync(0xffffffffu, sum[rr], 2);
    }
    if (tc == 0)
        #pragma unroll
        for (int rr = 0; rr < 4; rr++) red[(rr * 8 + gr) * 8 + w] = sum[rr];
    __syncthreads();
    float inv[4];
    #pragma unroll
    for (int rr = 0; rr < 4; rr++) {
        float z = red[(rr * 8 + gr) * 8];
        #pragma unroll
        for (int q = 1; q < 8; q++) z += red[(rr * 8 + gr) * 8 + q];
        inv[rr] = 1.0f / z;
    }
    #pragma unroll
    for (int jt = 0; jt < 8; jt++)
        #pragma unroll
        for (int mi = 0; mi < 2; mi++)
            #pragma unroll
            for (int ni = 0; ni < 2; ni++) {
                int col = jt * 128 + w * 16 + ni * 8 + 2 * tc;
                int r0 = mi * 16 + gr, r1 = mi * 16 + 8 + gr;
                *(__half2*)&smp[r0 * 1032 + col] = __floats2half2_rn(
                    acc[jt][mi][ni][0] * inv[mi * 2], acc[jt][mi][ni][1] * inv[mi * 2]);
                *(__half2*)&smp[r1 * 1032 + col] = __floats2half2_rn(
                    acc[jt][mi][ni][2] * inv[mi * 2 + 1], acc[jt][mi][ni][3] * inv[mi * 2 + 1]);
            }
    __syncthreads();

    // ================= P2: O_mu = p @ V_mu =================================
    pv_pass(Vmu);
    const int grow = b * N_ + iblk * 32 + rwarp * 16 + gr;
    const int gcolb = h * DH_ + cwarp * 16;
    __half2 omu_h[2][2];
    #pragma unroll
    for (int ni = 0; ni < 2; ni++) {
        omu_h[ni][0] = __floats2half2_rn(oacc[ni][0], oacc[ni][1]);
        omu_h[ni][1] = __floats2half2_rn(oacc[ni][2], oacc[ni][3]);
        int gcol = gcolb + ni * 8 + 2 * tc;
        *(__half2*)&g_mu_o[(size_t)grow * D_ + gcol]       = omu_h[ni][0];
        *(__half2*)&g_mu_o[(size_t)(grow + 8) * D_ + gcol] = omu_h[ni][1];
    }

    // ================= P3: dots-sg -> w (overwrite p in smem) ==============
    dots_pass(Ksg, smqb + 32 * 72 * 2, false);
    #pragma unroll
    for (int jt = 0; jt < 8; jt++)
        #pragma unroll
        for (int mi = 0; mi < 2; mi++)
            #pragma unroll
            for (int ni = 0; ni < 2; ni++) {
                int col = jt * 128 + w * 16 + ni * 8 + 2 * tc;
                #pragma unroll
                for (int half = 0; half < 2; half++) {
                    int row = mi * 16 + half * 8 + gr;
                    __half2 ph = *(__half2*)&smp[row * 1032 + col];
                    float p0 = __low2float(ph), p1 = __high2float(ph);
                    float j0 = p0 * (1.0f - p0), j1 = p1 * (1.0f - p1);
                    float w0 = j0 * j0 * acc[jt][mi][ni][2 * half] * SCALE_ * W_SCALE;
                    float w1 = j1 * j1 * acc[jt][mi][ni][2 * half + 1] * SCALE_ * W_SCALE;
                    *(__half2*)&smp[row * 1032 + col] = __floats2half2_rn(w0, w1);
                }
            }
    __syncthreads();

    // ================= P4: O_sg = w @ V_sg / W_SCALE + m2s_o ===============
    pv_pass(Vsg);
    #pragma unroll
    for (int ni = 0; ni < 2; ni++) {
        __half2 s01 = __floats2half2_rn(oacc[ni][0] * (1.0f / W_SCALE),
                                        oacc[ni][1] * (1.0f / W_SCALE));
        __half2 s23 = __floats2half2_rn(oacc[ni][2] * (1.0f / W_SCALE),
                                        oacc[ni][3] * (1.0f / W_SCALE));
        int gcol = gcolb + ni * 8 + 2 * tc;
        *(__half2*)&g_sg_o[(size_t)grow * D_ + gcol]       = s01;
        *(__half2*)&g_sg_o[(size_t)(grow + 8) * D_ + gcol] = s23;
        float2 mf0 = __half22float2(omu_h[ni][0]);
        float2 mf1 = __half22float2(omu_h[ni][1]);
        float2 sf0 = __half22float2(s01);
        float2 sf1 = __half22float2(s23);
        *(__half2*)&g_m2s_o[(size_t)grow * D_ + gcol] =
            __floats2half2_rn(fmaf(mf0.x, mf0.x, sf0.x), fmaf(mf0.y, mf0.y, sf0.y));
        *(__half2*)&g_m2s_o[(size_t)(grow + 8) * D_ + gcol] =
            __floats2half2_rn(fmaf(mf1.x, mf1.x, sf1.x), fmaf(mf1.y, mf1.y, sf1.y));
    }
}

// ------------------------------ prep weights -------------------------------
__device__ __forceinline__ float softplusf(float x) {
    return fmaxf(x, 0.0f) + log1pf(expf(-fabsf(x)));
}

__global__ void prep_weights_kernel(const float* __restrict__ Wqkv_mu,
                                    const float* __restrict__ Wqkv_raw,
                                    const float* __restrict__ Wout_mu,
                                    const float* __restrict__ Wout_raw) {
    int i = blockIdx.x * blockDim.x + threadIdx.x;
    const int nq2 = QKV_ * D_ / 2;
    if (i < nq2) {
        int e = 2 * i;
        float w0 = Wqkv_mu[e], w1 = Wqkv_mu[e + 1];
        *(__half2*)(g_Wq_mu  + e) = __floats2half2_rn(w0, w1);
        *(__half2*)(g_Wq_mu2 + e) = __floats2half2_rn(w0 * w0, w1 * w1);
        *(__half2*)(g_Wq_sig + e) = __floats2half2_rn(softplusf(Wqkv_raw[e]),
                                                      softplusf(Wqkv_raw[e + 1]));
    } else {
        int e = 2 * (i - nq2);
        if (e < D_ * D_) {
            float w0 = Wout_mu[e], w1 = Wout_mu[e + 1];
            *(__half2*)(g_Wo_mu  + e) = __floats2half2_rn(w0, w1);
            *(__half2*)(g_Wo_mu2 + e) = __floats2half2_rn(w0 * w0, w1 * w1);
            *(__half2*)(g_Wo_sig + e) = __floats2half2_rn(softplusf(Wout_raw[e]),
                                                          softplusf(Wout_raw[e + 1]));
        }
    }
}

// -------------------------------- layernorm --------------------------------
__global__ void layernorm_kernel(const float* __restrict__ mu,
                                 const float* __restrict__ sigma,
                                 const float* __restrict__ gamma,
                                 const float* __restrict__ beta) {
    const int row = blockIdx.x;
    const int t   = threadIdx.x;
    float4 m = ((const float4*)(mu + (size_t)row * D_))[t];

    float s  = m.x + m.y + m.z + m.w;
    float sq = m.x * m.x + m.y * m.y + m.z * m.z + m.w * m.w;

    __shared__ float red[256];
    red[t] = s; __syncthreads();
    #pragma unroll
    for (int o = 128; o > 0; o >>= 1) { if (t < o) red[t] += red[t + o]; __syncthreads(); }
    float mean = red[0] * (1.0f / D_);
    __syncthreads();
    red[t] = sq; __syncthreads();
    #pragma unroll
    for (int o = 128; o > 0; o >>= 1) { if (t < o) red[t] += red[t + o]; __syncthreads(); }
    float var = red[0] * (1.0f / D_) - mean * mean;
    float inv = rsqrtf(var + 1e-5f);

    const float4 sg = ((const float4*)(sigma + (size_t)row * D_))[t];
    const float4 gm = ((const float4*)gamma)[t];
    const float4 bt = ((const float4*)beta)[t];

    float4 mo, so, m2;
    mo.x = (m.x - mean) * inv * gm.x + bt.x;  so.x = sg.x * gm.x * gm.x * inv * inv;  m2.x = fmaf(mo.x, mo.x, so.x);
    mo.y = (m.y - mean) * inv * gm.y + bt.y;  so.y = sg.y * gm.y * gm.y * inv * inv;  m2.y = fmaf(mo.y, mo.y, so.y);
    mo.z = (m.z - mean) * inv * gm.z + bt.z;  so.z = sg.z * gm.z * gm.z * inv * inv;  m2.z = fmaf(mo.z, mo.z, so.z);
    mo.w = (m.w - mean) * inv * gm.w + bt.w;  so.w = sg.w * gm.w * gm.w * inv * inv;  m2.w = fmaf(mo.w, mo.w, so.w);

    const int e = row * D_ + t * 4;
    *(__half2*)(g_mu_n + e)     = __floats2half2_rn(mo.x, mo.y);
    *(__half2*)(g_mu_n + e + 2) = __floats2half2_rn(mo.z, mo.w);
    *(__half2*)(g_sg_n + e)     = __floats2half2_rn(so.x, so.y);
    *(__half2*)(g_sg_n + e + 2) = __floats2half2_rn(so.z, so.w);
    *(__half2*)(g_m2s + e)      = __floats2half2_rn(m2.x, m2.y);
    *(__half2*)(g_m2s + e + 2)  = __floats2half2_rn(m2.z, m2.w);
}

// --------------------------------- launch ----------------------------------
extern "C" void kernel_launch(void* const* d_in, const int* in_sizes, int n_in,
                              void* d_out, int out_size) {
    (void)in_sizes; (void)n_in; (void)out_size;
    const float* mu       = (const float*)d_in[0];
    const float* sigma    = (const float*)d_in[1];
    const float* gamma    = (const float*)d_in[2];
    const float* beta     = (const float*)d_in[3];
    const float* Wqkv_mu  = (const float*)d_in[4];
    const float* Wqkv_raw = (const float*)d_in[5];
    const float* Wout_mu  = (const float*)d_in[6];
    const float* Wout_raw = (const float*)d_in[7];
    float* out = (float*)d_out;

    __half *p_mu_n, *p_sg_n, *p_m2s, *p_wq_mu, *p_wq_sig, *p_wq_mu2;
    __half *p_wo_mu, *p_wo_sig, *p_wo_mu2, *p_mu_qkv, *p_sg_qkv;
    __half *p_mu_o, *p_sg_o, *p_m2so;
    cudaGetSymbolAddress((void**)&p_mu_n,   g_mu_n);
    cudaGetSymbolAddress((void**)&p_sg_n,   g_sg_n);
    cudaGetSymbolAddress((void**)&p_m2s,    g_m2s);
    cudaGetSymbolAddress((void**)&p_wq_mu,  g_Wq_mu);
    cudaGetSymbolAddress((void**)&p_wq_sig, g_Wq_sig);
    cudaGetSymbolAddress((void**)&p_wq_mu2, g_Wq_mu2);
    cudaGetSymbolAddress((void**)&p_wo_mu,  g_Wo_mu);
    cudaGetSymbolAddress((void**)&p_wo_sig, g_Wo_sig);
    cudaGetSymbolAddress((void**)&p_wo_mu2, g_Wo_mu2);
    cudaGetSymbolAddress((void**)&p_mu_qkv, g_mu_qkv);
    cudaGetSymbolAddress((void**)&p_sg_qkv, g_sg_qkv);
    cudaGetSymbolAddress((void**)&p_mu_o,   g_mu_o);
    cudaGetSymbolAddress((void**)&p_sg_o,   g_sg_o);
    cudaGetSymbolAddress((void**)&p_m2so,   g_m2s_o);

    const int S_BIG = 3 * (128 * 40 + 128 * 40) * 2;   // 61440 B
    cudaFuncSetAttribute(gemm16h_dual_kernel, cudaFuncAttributeMaxDynamicSharedMemorySize, S_BIG);
    cudaFuncSetAttribute(gemm16f_dual_kernel, cudaFuncAttributeMaxDynamicSharedMemorySize, S_BIG);
    cudaFuncSetAttribute(fused_attn_kernel, cudaFuncAttributeMaxDynamicSharedMemorySize, FA_SMEM);

    // 1. weight transforms -> fp16
    prep_weights_kernel<<<(QKV_ * D_ + D_ * D_) / 2 / 256, 256>>>(
        Wqkv_mu, Wqkv_raw, Wout_mu, Wout_raw);

    // 2. layernorm (+ mu^2+sigma) -> fp16
    layernorm_kernel<<<M_, 256>>>(mu, sigma, gamma, beta);

    // 3. QKV projections: ONE launch, z=0 = sigma (longer), z=1 = mu
    {
        GemmJobH jsg = { p_sg_qkv, p_m2s, p_wq_sig, p_sg_n, p_wq_mu2, 32, 32 };
        GemmJobH jmu = { p_mu_qkv, p_mu_n, p_wq_mu,  p_mu_n, p_wq_mu,  32, 0 };
        dim3 gq(QKV_ / 128, M_ / 128, 2);
        gemm16h_dual_kernel<<<gq, 256, S_BIG>>>(jsg, jmu, D_, D_, QKV_);
    }

    // 4-7. fused attention middle (dots, softmax, PV, m2s_o)
    fused_attn_kernel<<<dim3(N_ / 32, BH_), 256, FA_SMEM>>>();

    // 8. output projection: ONE launch, z=0 = sigma (longer), z=1 = mu
    {
        GemmJobF jsg = { out + M_ * D_, p_m2so, p_wo_sig, p_sg_o, p_wo_mu2, 32, 32 };
        GemmJobF jmu = { out,           p_mu_o, p_wo_mu,  p_mu_o, p_wo_mu,  32, 0 };
        dim3 go(D_ / 128, M_ / 128, 2);
        gemm16f_dual_kernel<<<go, 256, S_BIG>>>(jsg, jmu, D_, D_, D_);
    }
}